// round 16
// baseline (speedup 1.0000x reference)
#include <cuda_runtime.h>
#include <cuda_bf16.h>
#include <cstdint>

// ---------------------------------------------------------------------------
// Problem constants
// ---------------------------------------------------------------------------
#define BATCH 16
#define TLEN  4096
#define NTOK  (BATCH * TLEN)   // 65536
#define DDIM  512
#define EDIM  256
#define NCODE 1024

#define N_ZOUT   ((size_t)NTOK * DDIM)
#define OFF_L1   (N_ZOUT)
#define OFF_L2   (N_ZOUT + 16)
#define OFF_CODE (N_ZOUT + 32)
#define OUT_FULL (N_ZOUT + 32 + NTOK)

#define TILE_M 64
#define NTILES (NTOK / TILE_M)   // 1024
#define TAU 0.02f

typedef unsigned long long u64;
typedef unsigned int u32;

// ---------------------------------------------------------------------------
// Device scratch
// ---------------------------------------------------------------------------
__device__ __nv_bfloat16 g_wdhi[EDIM * DDIM];   // w_down [e][k] hi
__device__ __nv_bfloat16 g_wdlo[EDIM * DDIM];
__device__ __nv_bfloat16 g_cbhi[NCODE * EDIM];  // codebook [j][e] hi
__device__ __nv_bfloat16 g_cblo[NCODE * EDIM];
__device__ float g_cnh[NCODE];                  // 0.5*||c_j||^2
__device__ float g_M[NCODE * DDIM];             // codebook @ w_up^T
__device__ float g_lossTok[NTOK];
__device__ int   g_rescue[NTOK];
__device__ int   g_nrescue;

// ---------------------------------------------------------------------------
// helpers
// ---------------------------------------------------------------------------
__device__ __forceinline__ u32 smem_u32(const void* p) {
    u32 a;
    asm("{ .reg .u64 t; cvta.to.shared.u64 t, %1; cvt.u32.u64 %0, t; }" : "=r"(a) : "l"(p));
    return a;
}
__device__ __forceinline__ void ldsm4(u32 addr, u32& r0, u32& r1, u32& r2, u32& r3) {
    asm volatile("ldmatrix.sync.aligned.m8n8.x4.shared.b16 {%0,%1,%2,%3}, [%4];"
                 : "=r"(r0), "=r"(r1), "=r"(r2), "=r"(r3) : "r"(addr));
}
__device__ __forceinline__ void ldsm2(u32 addr, u32& r0, u32& r1) {
    asm volatile("ldmatrix.sync.aligned.m8n8.x2.shared.b16 {%0,%1}, [%2];"
                 : "=r"(r0), "=r"(r1) : "r"(addr));
}
__device__ __forceinline__ void mma16816(float* c, const u32* a, const u32* b) {
    asm volatile(
        "mma.sync.aligned.m16n8k16.row.col.f32.bf16.bf16.f32 "
        "{%0,%1,%2,%3}, {%4,%5,%6,%7}, {%8,%9}, {%0,%1,%2,%3};"
        : "+f"(c[0]), "+f"(c[1]), "+f"(c[2]), "+f"(c[3])
        : "r"(a[0]), "r"(a[1]), "r"(a[2]), "r"(a[3]), "r"(b[0]), "r"(b[1]));
}
__device__ __forceinline__ u32 pack_hi(float a, float b) {
    __nv_bfloat162 t; t.x = __float2bfloat16(a); t.y = __float2bfloat16(b);
    return *(u32*)&t;
}
__device__ __forceinline__ u32 pack_lo(float a, float b) {
    __nv_bfloat162 t;
    t.x = __float2bfloat16(a - __bfloat162float(__float2bfloat16(a)));
    t.y = __float2bfloat16(b - __bfloat162float(__float2bfloat16(b)));
    return *(u32*)&t;
}
__device__ __forceinline__ void cp16(u32 dst, const void* src) {
    asm volatile("cp.async.ca.shared.global [%0], [%1], 16;" :: "r"(dst), "l"(src));
}
#define CP_COMMIT() asm volatile("cp.async.commit_group;" ::: "memory")
#define CP_WAIT1()  asm volatile("cp.async.wait_group 1;" ::: "memory")

// ---------------------------------------------------------------------------
// Merged prep kernel (identical numerics to R13/R14)
// ---------------------------------------------------------------------------
__global__ void k_prep_all(const float* __restrict__ wd, const float* __restrict__ cb,
                           const float* __restrict__ wu) {
    __shared__ float scb[8 * 256];
    __shared__ float swu[32 * 260];
    int b = blockIdx.x, tid = threadIdx.x;
    if (b < 512) {
        int idx = b * 256 + tid;
        float v = wd[idx];
        __nv_bfloat16 hi = __float2bfloat16(v);
        g_wdhi[idx] = hi;
        g_wdlo[idx] = __float2bfloat16(v - __bfloat162float(hi));
    } else if (b < 1536) {
        int idx = (b - 512) * 256 + tid;
        float v = cb[idx];
        __nv_bfloat16 hi = __float2bfloat16(v);
        g_cbhi[idx] = hi;
        g_cblo[idx] = __float2bfloat16(v - __bfloat162float(hi));
    } else if (b < 1540) {
        int j = (b - 1536) * 256 + tid;
        if (j == 0) g_nrescue = 0;
        if (j < NCODE) {
            const float4* r = (const float4*)(cb + (size_t)j * EDIM);
            float s = 0.f;
#pragma unroll 8
            for (int q = 0; q < EDIM / 4; q++) {
                float4 v = r[q];
                s += v.x * v.x + v.y * v.y + v.z * v.z + v.w * v.w;
            }
            g_cnh[j] = 0.5f * s;
        }
    } else {
        int mb = b - 1540;
        int j0 = (mb >> 4) * 8;
        int d0 = (mb & 15) * 32;
#pragma unroll
        for (int r = 0; r < 2; r++) {
            int idx = tid + r * 256;
            int row = idx >> 6, q = (idx & 63) << 2;
            *(float4*)&scb[row * 256 + q] = *(const float4*)&cb[(size_t)(j0 + row) * EDIM + q];
        }
#pragma unroll
        for (int r = 0; r < 8; r++) {
            int idx = tid + r * 256;
            int row = idx >> 6, q = (idx & 63) << 2;
            *(float4*)&swu[row * 260 + q] = *(const float4*)&wu[(size_t)(d0 + row) * EDIM + q];
        }
        __syncthreads();
        int jl = tid >> 5, dl = tid & 31;
        float s = 0.f;
#pragma unroll 16
        for (int e = 0; e < 256; e += 4) {
            float4 a = *(float4*)&scb[jl * 256 + e];
            float4 bq = *(float4*)&swu[dl * 260 + e];
            s += a.x * bq.x + a.y * bq.y + a.z * bq.z + a.w * bq.w;
        }
        g_M[(size_t)(j0 + jl) * DDIM + d0 + dl] = s;
    }
}

// ---------------------------------------------------------------------------
// Main kernel: same math as R12-R14 (bit-identical k16-step order), with
// phase-1 register prefetch and phase-2 cp.async double-buffered B tiles.
// Smem: ZEHI[64][264] @0 | ZELO @33792 | staging @67584:
//   phase1 (single buf): AZHI 3072 | AZLO 3072 | BWHI 12288 | BWLO 12288
//   phase2 (double buf): buf p @67584+p*20480: BHI[128][40] 10240 | BLO 10240
// total dynamic = 108544 -> 2 CTAs/SM.
// ---------------------------------------------------------------------------
#define OFF_ZEHI 0
#define OFF_ZELO 33792
#define OFF_P    67584
#define OFF_AZHI (OFF_P)
#define OFF_AZLO (OFF_P + 3072)
#define OFF_BWHI (OFF_P + 6144)
#define OFF_BWLO (OFF_P + 18432)
#define P2_BUF   20480
#define P2_BHI   0
#define P2_BLO   10240
#define SM_TOTAL 108544

__global__ __launch_bounds__(256, 2) void vq_mma(
    const float* __restrict__ z, float* __restrict__ out, int write_extra)
{
    extern __shared__ char sm[];
    __shared__ float s_min[8][64];
    __shared__ float s_min2[8][64];
    __shared__ int   s_idx[8][64];
    __shared__ float s_zn[8][64];
    __shared__ int   s_code[64];

    const int tid = threadIdx.x;
    const int w = tid >> 5, lane = tid & 31;
    const int tok0 = blockIdx.x * TILE_M;
    const u32 smb = smem_u32(sm);

    float acc[4][4][4];
#pragma unroll
    for (int m = 0; m < 4; m++)
#pragma unroll
        for (int nt = 0; nt < 4; nt++)
#pragma unroll
            for (int c = 0; c < 4; c++) acc[m][nt][c] = 0.f;

    // ================= Phase 1: z_e = z @ w_down^T (reg-prefetch pipeline) ===
    const int zrow = tid >> 2, zc4 = tid & 3;
    const int wrow = tid >> 1, wq = tid & 1;          // j=0 slice (rows 0..127)
    const int wrow2 = (tid + 256) >> 1, wq2 = (tid + 256) & 1;  // rows 128..255
    float4 pz;
    uint4 pwh0, pwh1, pwl0, pwl1;
    {   // preload kc=0
        pz = *(const float4*)&z[(size_t)(tok0 + zrow) * DDIM + zc4 * 4];
        pwh0 = *(const uint4*)&g_wdhi[wrow * DDIM + wq * 8];
        pwh1 = *(const uint4*)&g_wdhi[wrow2 * DDIM + wq2 * 8];
        pwl0 = *(const uint4*)&g_wdlo[wrow * DDIM + wq * 8];
        pwl1 = *(const uint4*)&g_wdlo[wrow2 * DDIM + wq2 * 8];
    }
#pragma unroll 1
    for (int kc = 0; kc < 32; kc++) {
        {   // STS prefetched regs
            u32 off = (u32)(zrow * 24 + zc4 * 4) * 2;
            *(uint2*)(sm + OFF_AZHI + off) = make_uint2(pack_hi(pz.x, pz.y), pack_hi(pz.z, pz.w));
            *(uint2*)(sm + OFF_AZLO + off) = make_uint2(pack_lo(pz.x, pz.y), pack_lo(pz.z, pz.w));
            u32 d0 = (u32)(wrow * 24 + wq * 8) * 2;
            u32 d1 = (u32)(wrow2 * 24 + wq2 * 8) * 2;
            *(uint4*)(sm + OFF_BWHI + d0) = pwh0;
            *(uint4*)(sm + OFF_BWHI + d1) = pwh1;
            *(uint4*)(sm + OFF_BWLO + d0) = pwl0;
            *(uint4*)(sm + OFF_BWLO + d1) = pwl1;
        }
        __syncthreads();
        if (kc + 1 < 32) {   // prefetch next chunk (latency hidden behind mma)
            pz = *(const float4*)&z[(size_t)(tok0 + zrow) * DDIM + (kc + 1) * 16 + zc4 * 4];
            pwh0 = *(const uint4*)&g_wdhi[wrow * DDIM + (kc + 1) * 16 + wq * 8];
            pwh1 = *(const uint4*)&g_wdhi[wrow2 * DDIM + (kc + 1) * 16 + wq2 * 8];
            pwl0 = *(const uint4*)&g_wdlo[wrow * DDIM + (kc + 1) * 16 + wq * 8];
            pwl1 = *(const uint4*)&g_wdlo[wrow2 * DDIM + (kc + 1) * 16 + wq2 * 8];
        }
        {
            u32 bh[4][2], bl[4][2];
#pragma unroll
            for (int nt = 0; nt < 4; nt++) {
                u32 a = (u32)((w * 32 + nt * 8 + (lane & 7)) * 24 + ((lane >> 3) & 1) * 8) * 2;
                ldsm2(smb + OFF_BWHI + a, bh[nt][0], bh[nt][1]);
                ldsm2(smb + OFF_BWLO + a, bl[nt][0], bl[nt][1]);
            }
#pragma unroll
            for (int m = 0; m < 4; m++) {
                u32 ah[4], al[4];
                u32 aA = (u32)((m * 16 + (lane & 15)) * 24 + (lane >> 4) * 8) * 2;
                ldsm4(smb + OFF_AZHI + aA, ah[0], ah[1], ah[2], ah[3]);
                ldsm4(smb + OFF_AZLO + aA, al[0], al[1], al[2], al[3]);
#pragma unroll
                for (int nt = 0; nt < 4; nt++) {
                    mma16816(acc[m][nt], ah, bh[nt]);
                    mma16816(acc[m][nt], al, bh[nt]);
                    mma16816(acc[m][nt], ah, bl[nt]);
                }
            }
        }
        __syncthreads();
    }

    // ---- phase-1 epilogue (unchanged) ----
    {
        float znp[8];
#pragma unroll
        for (int s = 0; s < 8; s++) znp[s] = 0.f;
#pragma unroll
        for (int m = 0; m < 4; m++) {
#pragma unroll
            for (int nt = 0; nt < 4; nt++) {
                float c0 = acc[m][nt][0], c1 = acc[m][nt][1];
                float c2 = acc[m][nt][2], c3 = acc[m][nt][3];
                znp[m * 2]     += c0 * c0 + c1 * c1;
                znp[m * 2 + 1] += c2 * c2 + c3 * c3;
                int e0 = w * 32 + nt * 8 + 2 * (lane & 3);
                int r1 = m * 16 + (lane >> 2);
                u32 o1 = (u32)(r1 * 264 + e0) * 2;
                u32 o2 = (u32)((r1 + 8) * 264 + e0) * 2;
                *(u32*)(sm + OFF_ZEHI + o1) = pack_hi(c0, c1);
                *(u32*)(sm + OFF_ZELO + o1) = pack_lo(c0, c1);
                *(u32*)(sm + OFF_ZEHI + o2) = pack_hi(c2, c3);
                *(u32*)(sm + OFF_ZELO + o2) = pack_lo(c2, c3);
            }
        }
#pragma unroll
        for (int s = 0; s < 8; s++) {
            znp[s] += __shfl_xor_sync(0xffffffffu, znp[s], 1);
            znp[s] += __shfl_xor_sync(0xffffffffu, znp[s], 2);
        }
        if ((lane & 3) == 0) {
#pragma unroll
            for (int m = 0; m < 4; m++) {
                int r1 = m * 16 + (lane >> 2);
                s_zn[w][r1]     = znp[m * 2];
                s_zn[w][r1 + 8] = znp[m * 2 + 1];
            }
        }
    }
    __syncthreads();

    // ================= Phase 2: scores vs 1024 codes (cp.async dbl-buffer) ===
    float minv[8], minv2[8]; int mini[8];
#pragma unroll
    for (int s = 0; s < 8; s++) { minv[s] = 3.4e38f; minv2[s] = 3.4e38f; mini[s] = 0; }

    // staging map (FIXED): chunk = [128 codes][32 e] = 128 rows x 64B.
    // 512 x 16B transfers per hi/lo array; thread handles j=0,1:
    //   idx = tid + j*256 -> row = idx>>2 (0..127), q = idx&3 (0..3)
    const int brow = tid >> 2, bq = tid & 3;           // rows 0..63
    const int brow2 = 64 + (tid >> 2);                 // rows 64..127 (same bq)
    {   // prologue: issue it=0 (jc=0, ec=0)
        cp16(smb + OFF_P + P2_BHI + (u32)(brow * 40 + bq * 8) * 2,
             &g_cbhi[(size_t)brow * EDIM + bq * 8]);
        cp16(smb + OFF_P + P2_BHI + (u32)(brow2 * 40 + bq * 8) * 2,
             &g_cbhi[(size_t)brow2 * EDIM + bq * 8]);
        cp16(smb + OFF_P + P2_BLO + (u32)(brow * 40 + bq * 8) * 2,
             &g_cblo[(size_t)brow * EDIM + bq * 8]);
        cp16(smb + OFF_P + P2_BLO + (u32)(brow2 * 40 + bq * 8) * 2,
             &g_cblo[(size_t)brow2 * EDIM + bq * 8]);
        CP_COMMIT();
    }
    float acc2[4][2][4];
#pragma unroll 1
    for (int it = 0; it < 64; it++) {
        int jc = it >> 3, ec = it & 7;
        int p = it & 1;
        u32 bufb = smb + OFF_P + (u32)p * P2_BUF;
        if (ec == 0) {
#pragma unroll
            for (int m = 0; m < 4; m++)
#pragma unroll
                for (int nt = 0; nt < 2; nt++)
#pragma unroll
                    for (int c = 0; c < 4; c++) acc2[m][nt][c] = 0.f;
        }
        if (it + 1 < 64) {   // issue next chunk into other buffer
            int jn = (it + 1) >> 3, en = (it + 1) & 7;
            u32 nb = smb + OFF_P + (u32)((it + 1) & 1) * P2_BUF;
            const __nv_bfloat16* sh = &g_cbhi[(size_t)(jn * 128) * EDIM + en * 32];
            const __nv_bfloat16* sl = &g_cblo[(size_t)(jn * 128) * EDIM + en * 32];
            cp16(nb + P2_BHI + (u32)(brow * 40 + bq * 8) * 2,  sh + (size_t)brow * EDIM + bq * 8);
            cp16(nb + P2_BHI + (u32)(brow2 * 40 + bq * 8) * 2, sh + (size_t)brow2 * EDIM + bq * 8);
            cp16(nb + P2_BLO + (u32)(brow * 40 + bq * 8) * 2,  sl + (size_t)brow * EDIM + bq * 8);
            cp16(nb + P2_BLO + (u32)(brow2 * 40 + bq * 8) * 2, sl + (size_t)brow2 * EDIM + bq * 8);
            CP_COMMIT();
            CP_WAIT1();      // current buffer's group complete (issued 1 step ago)
        } else {
            asm volatile("cp.async.wait_group 0;" ::: "memory");
        }
        __syncthreads();
#pragma unroll
        for (int ks = 0; ks < 2; ks++) {
            u32 bh[2][2], bl[2][2];
#pragma unroll
            for (int nt = 0; nt < 2; nt++) {
                u32 a = (u32)((w * 16 + nt * 8 + (lane & 7)) * 40 + ks * 16 + ((lane >> 3) & 1) * 8) * 2;
                ldsm2(bufb + P2_BHI + a, bh[nt][0], bh[nt][1]);
                ldsm2(bufb + P2_BLO + a, bl[nt][0], bl[nt][1]);
            }
#pragma unroll
            for (int m = 0; m < 4; m++) {
                u32 ah[4], al[4];
                u32 aA = (u32)((m * 16 + (lane & 15)) * 264 + ec * 32 + ks * 16 + (lane >> 4) * 8) * 2;
                ldsm4(smb + OFF_ZEHI + aA, ah[0], ah[1], ah[2], ah[3]);
                ldsm4(smb + OFF_ZELO + aA, al[0], al[1], al[2], al[3]);
#pragma unroll
                for (int nt = 0; nt < 2; nt++) {
                    mma16816(acc2[m][nt], ah, bh[nt]);
                    mma16816(acc2[m][nt], al, bh[nt]);
                    mma16816(acc2[m][nt], ah, bl[nt]);
                }
            }
        }
        __syncthreads();     // all warps done with buf[p] before it's rewritten
        if (ec == 7) {       // jc complete: scan (identical to R12-R14)
            float cn[4];
#pragma unroll
            for (int nt = 0; nt < 2; nt++) {
                int jb = jc * 128 + w * 16 + nt * 8 + 2 * (lane & 3);
                cn[nt * 2]     = __ldg(&g_cnh[jb]);
                cn[nt * 2 + 1] = __ldg(&g_cnh[jb + 1]);
            }
#pragma unroll
            for (int m = 0; m < 4; m++) {
#pragma unroll
                for (int nt = 0; nt < 2; nt++) {
#pragma unroll
                    for (int c = 0; c < 4; c++) {
                        float s = cn[nt * 2 + (c & 1)] - acc2[m][nt][c];
                        int code = jc * 128 + w * 16 + nt * 8 + 2 * (lane & 3) + (c & 1);
                        int slot = m * 2 + (c >> 1);
                        if (s < minv[slot]) { minv2[slot] = minv[slot]; minv[slot] = s; mini[slot] = code; }
                        else if (s < minv2[slot]) { minv2[slot] = s; }
                    }
                }
            }
        }
    }

#pragma unroll
    for (int s = 0; s < 8; s++) {
#pragma unroll
        for (int off = 1; off <= 2; off <<= 1) {
            float ov  = __shfl_xor_sync(0xffffffffu, minv[s], off);
            float ov2 = __shfl_xor_sync(0xffffffffu, minv2[s], off);
            int   oi  = __shfl_xor_sync(0xffffffffu, mini[s], off);
            float nv2 = fminf(fmaxf(minv[s], ov), fminf(minv2[s], ov2));
            if (ov < minv[s] || (ov == minv[s] && oi < mini[s])) { minv[s] = ov; mini[s] = oi; }
            minv2[s] = nv2;
        }
    }
    if ((lane & 3) == 0) {
#pragma unroll
        for (int m = 0; m < 4; m++) {
            int r1 = m * 16 + (lane >> 2);
            s_min[w][r1] = minv[m * 2];      s_min2[w][r1] = minv2[m * 2];      s_idx[w][r1] = mini[m * 2];
            s_min[w][r1 + 8] = minv[m * 2 + 1]; s_min2[w][r1 + 8] = minv2[m * 2 + 1]; s_idx[w][r1 + 8] = mini[m * 2 + 1];
        }
    }
    __syncthreads();

    if (tid < 64) {
        float v = s_min[0][tid], v2 = s_min2[0][tid], zn = s_zn[0][tid];
        int id = s_idx[0][tid];
#pragma unroll
        for (int ww = 1; ww < 8; ww++) {
            float ov = s_min[ww][tid], ov2 = s_min2[ww][tid];
            int oi = s_idx[ww][tid];
            float nv2 = fminf(fmaxf(v, ov), fminf(v2, ov2));
            if (ov < v || (ov == v && oi < id)) { v = ov; id = oi; }
            v2 = nv2;
            zn += s_zn[ww][tid];
        }
        int tok = tok0 + tid;
        g_lossTok[tok] = 2.f * v + zn;
        if (write_extra) out[OFF_CODE + tok] = (float)id;
        s_code[tid] = id;
        if (v2 - v < TAU) {
            int slot = atomicAdd(&g_nrescue, 1);
            g_rescue[slot] = tok;
        }
    }
    __syncthreads();

#pragma unroll 1
    for (int j = 0; j < 32; j++) {
        int idx = tid + j * 256;
        int row = idx >> 7, q = idx & 127;
        int c = s_code[row];
        float4 vv = *(const float4*)&g_M[(size_t)c * DDIM + q * 4];
        *(float4*)&out[(size_t)(tok0 + row) * DDIM + q * 4] = vv;
    }
}

// ---------------------------------------------------------------------------
// Rescue v4 (unchanged from R15): bit-exact chains, 256 threads/block, RB=4.
// ---------------------------------------------------------------------------
#define RB 4
__global__ __launch_bounds__(256) void k_rescue(
    const float* __restrict__ z, const float* __restrict__ cb,
    const float* __restrict__ wd, float* __restrict__ out, int write_extra)
{
    __shared__ float zr[RB][512];
    __shared__ float ze[RB][256];
    __shared__ float rbd[RB][256];
    __shared__ int   rbi[RB][256];
    __shared__ float rzn[RB][256];
    __shared__ int   stok[RB];

    int tid = threadIdx.x;
    int n = g_nrescue;
    if (n <= 0) return;
    for (int base = blockIdx.x * RB; base < n; base += gridDim.x * RB) {
        if (tid < RB) {
            int idx = base + tid; if (idx > n - 1) idx = n - 1;
            stok[tid] = g_rescue[idx];
        }
        __syncthreads();
        if (tid < 128) {
#pragma unroll
            for (int t = 0; t < RB; t++)
                ((float4*)zr[t])[tid] = ((const float4*)&z[(size_t)stok[t] * DDIM])[tid];
        }
        __syncthreads();

        {   // exact z_e: thread -> column e = tid, ascending-k fp32 FMA chain
            const float* w0 = wd + (size_t)tid * DDIM;
            float s0[RB];
#pragma unroll
            for (int t = 0; t < RB; t++) s0[t] = 0.f;
#pragma unroll 2
            for (int kb = 0; kb < 512; kb += 8) {
                float a0[8];
#pragma unroll
                for (int q = 0; q < 8; q++) a0[q] = w0[kb + q];
#pragma unroll
                for (int t = 0; t < RB; t++) {
#pragma unroll
                    for (int q = 0; q < 8; q++)
                        s0[t] = __fmaf_rn(zr[t][kb + q], a0[q], s0[t]);
                }
            }
#pragma unroll
            for (int t = 0; t < RB; t++) ze[t][tid] = s0[t];
        }
        __syncthreads();

        {   // exact scores: thread owns codes {c*256+tid}, ascending c
            float dot[4][RB];
#pragma unroll
            for (int c = 0; c < 4; c++)
#pragma unroll
                for (int t = 0; t < RB; t++) dot[c][t] = 0.f;
            float znp[RB];
#pragma unroll
            for (int t = 0; t < RB; t++) { float a = ze[t][tid]; znp[t] = a * a; }
#pragma unroll 2
            for (int kb = 0; kb < 256; kb += 8) {
                float zreg[RB][8];
#pragma unroll
                for (int t = 0; t < RB; t++)
#pragma unroll
                    for (int q = 0; q < 8; q++) zreg[t][q] = ze[t][kb + q];
#pragma unroll
                for (int c = 0; c < 4; c++) {
                    const float* cr = cb + (size_t)(c * 256 + tid) * EDIM;
                    float c8[8];
#pragma unroll
                    for (int q = 0; q < 8; q++) c8[q] = cr[kb + q];
#pragma unroll
                    for (int t = 0; t < RB; t++)
#pragma unroll
                        for (int q = 0; q < 8; q++)
                            dot[c][t] = __fmaf_rn(zreg[t][q], c8[q], dot[c][t]);
                }
            }
            float best[RB]; int bidx[RB];
#pragma unroll
            for (int t = 0; t < RB; t++) { best[t] = 3.4e38f; bidx[t] = 0; }
#pragma unroll
            for (int c = 0; c < 4; c++) {
                int j = c * 256 + tid;
                float cn = __ldg(&g_cnh[j]);
#pragma unroll
                for (int t = 0; t < RB; t++) {
                    float s = cn - dot[c][t];
                    if (s < best[t]) { best[t] = s; bidx[t] = j; }
                }
            }
#pragma unroll
            for (int t = 0; t < RB; t++) {
                rbd[t][tid] = best[t]; rbi[t][tid] = bidx[t]; rzn[t][tid] = znp[t];
            }
        }
        __syncthreads();
        for (int off = 128; off > 0; off >>= 1) {
            if (tid < off) {
#pragma unroll
                for (int t = 0; t < RB; t++) {
                    float ov = rbd[t][tid + off]; int oi = rbi[t][tid + off];
                    if (ov < rbd[t][tid] || (ov == rbd[t][tid] && oi < rbi[t][tid])) {
                        rbd[t][tid] = ov; rbi[t][tid] = oi;
                    }
                    rzn[t][tid] += rzn[t][tid + off];
                }
            }
            __syncthreads();
        }
#pragma unroll
        for (int t = 0; t < RB; t++) {
            int tok = stok[t]; int cw = rbi[t][0];
            if (tid < 128)
                ((float4*)&out[(size_t)tok * DDIM])[tid] =
                    ((const float4*)&g_M[(size_t)cw * DDIM])[tid];
            if (tid == 0) {
                g_lossTok[tok] = 2.f * rbd[t][0] + rzn[t][0];
                if (write_extra) out[OFF_CODE + tok] = (float)cw;
            }
        }
        __syncthreads();
    }
}

// ---------------------------------------------------------------------------
__global__ void k_finalize(float* __restrict__ out) {
    __shared__ float p[128];
    int b = blockIdx.x, tid = threadIdx.x;
    float s = 0.f;
    for (int q = 0; q < 32; q++) s += g_lossTok[b * TLEN + tid * 32 + q];
    p[tid] = s;
    __syncthreads();
    for (int off = 64; off > 0; off >>= 1) {
        if (tid < off) p[tid] += p[tid + off];
        __syncthreads();
    }
    if (tid == 0) {
        float loss = p[0] * (1.0f / ((float)TLEN * (float)EDIM));
        out[OFF_L1 + b] = loss;
        out[OFF_L2 + b] = loss;
    }
}

// ---------------------------------------------------------------------------
extern "C" void kernel_launch(void* const* d_in, const int* in_sizes, int n_in,
                              void* d_out, int out_size) {
    const float* z  = (const float*)d_in[0];
    const float* cb = (const float*)d_in[1];
    const float* wd = (const float*)d_in[2];
    const float* wu = (const float*)d_in[3];
    float* out = (float*)d_out;

    int write_extra = ((size_t)out_size >= OUT_FULL) ? 1 : 0;

    cudaFuncSetAttribute(vq_mma, cudaFuncAttributeMaxDynamicSharedMemorySize, SM_TOTAL);

    k_prep_all<<<3588, 256>>>(wd, cb, wu);
    vq_mma<<<NTILES, 256, SM_TOTAL>>>(z, out, write_extra);
    k_rescue<<<1024, 256>>>(z, cb, wd, out, write_extra);
    k_finalize<<<BATCH, 128>>>(out);
}